// round 3
// baseline (speedup 1.0000x reference)
#include <cuda_runtime.h>

// EMA y_t = (1-w)*y_{t-1} + w*x_t  — single-pass decoupled-lookback scan, v2.
// Vectorized: thread = 4 channels (float4 / 128-bit mem ops), packed f32x2 FMA.
// Block tile = 32 timesteps x 256 channels (4 sub-chunks x 8 t/thread).
// Stash lives in shared memory (32KB/CTA); lookback on 64 threads, 4-pred batches.

typedef unsigned long long u64;

#define TT   8192
#define CC   256
#define LT   8            // timesteps per thread
#define SUBS 4            // sub-chunks per block
#define CHT  (LT * SUBS)  // 32 timesteps per chunk/block
#define NCH  (TT / CHT)   // 256 chunks per batch
#define MAXB 16

// carry word per (b, chunk, channel): high 32 = flag (0/1 agg/2 prefix), low 32 = float bits
__device__ u64 g_carry[MAXB * NCH * CC];

// ---- packed f32x2 helpers ----
__device__ __forceinline__ u64 f2fma(u64 a, u64 b, u64 c) {
    u64 d; asm("fma.rn.f32x2 %0, %1, %2, %3;" : "=l"(d) : "l"(a), "l"(b), "l"(c)); return d;
}
__device__ __forceinline__ u64 f2mul(u64 a, u64 b) {
    u64 d; asm("mul.rn.f32x2 %0, %1, %2;" : "=l"(d) : "l"(a), "l"(b)); return d;
}
__device__ __forceinline__ u64 pk(float lo, float hi) {
    u64 d; asm("mov.b64 %0, {%1, %2};" : "=l"(d) : "f"(lo), "f"(hi)); return d;
}
__device__ __forceinline__ float lo32(u64 v) { return __uint_as_float((unsigned)v); }
__device__ __forceinline__ float hi32(u64 v) { return __uint_as_float((unsigned)(v >> 32)); }

__global__ void ema_clear_kernel() {
    int i = blockIdx.x * blockDim.x + threadIdx.x;
    ((ulonglong2*)g_carry)[i] = make_ulonglong2(0ULL, 0ULL);
}

__global__ __launch_bounds__(256, 4) void ema_scan_kernel(
    const float* __restrict__ x,
    const float* __restrict__ y0,
    const float* __restrict__ smooth,
    float* __restrict__ out)
{
    __shared__ ulonglong2 s_x[LT][256];   // stash: [row][tid], conflict-free 16B lanes
    __shared__ ulonglong2 s_e[SUBS][64];  // per-sub aggregates per channel-quad
    __shared__ ulonglong2 s_bs[64];       // block-start per channel-quad

    const int bid = blockIdx.x;
    const int k = bid % NCH;      // chunk (fast dim -> preds have lower blockIdx)
    const int b = bid / NCH;
    const int tid = threadIdx.x;
    const int c4 = tid & 63;      // channel-quad
    const int sub = tid >> 6;     // sub-chunk (uniform per warp)
    const int ch0 = c4 * 4;

    // per-channel coefficients, packed
    float4 sm = ((const float4*)smooth)[c4];
    float w0 = fminf(fmaxf(sm.x, 0.f), 1.f), w1 = fminf(fmaxf(sm.y, 0.f), 1.f);
    float w2 = fminf(fmaxf(sm.z, 0.f), 1.f), w3 = fminf(fmaxf(sm.w, 0.f), 1.f);
    const u64 w01 = pk(w0, w1), w23 = pk(w2, w3);
    const u64 a01 = pk(1.f - w0, 1.f - w1), a23 = pk(1.f - w2, 1.f - w3);
    u64 t;
    t = f2mul(a01, a01); t = f2mul(t, t); const u64 A8_01 = f2mul(t, t);  // a^8
    t = f2mul(a23, a23); t = f2mul(t, t); const u64 A8_23 = f2mul(t, t);

    const size_t base = ((size_t)(b * TT + k * CHT + sub * LT)) * CC + ch0;
    const ulonglong2* xp = (const ulonglong2*)x + (base >> 2);

    // ---- Phase A: stream chunk into smem stash, compute zero-start aggregate ----
    u64 e01 = 0ULL, e23 = 0ULL;  // {0.0f, 0.0f}
#pragma unroll
    for (int i = 0; i < LT; i++) {
        ulonglong2 xv = __ldcs(xp + i * (CC / 4));
        s_x[i][tid] = xv;
        e01 = f2fma(a01, e01, f2mul(w01, xv.x));
        e23 = f2fma(a23, e23, f2mul(w23, xv.y));
    }
    s_e[sub][c4] = make_ulonglong2(e01, e23);
    __syncthreads();

    if (sub == 0) {
        // compose block aggregate E over the 4 sub-chunks
        u64 E01, E23;
        { ulonglong2 es = s_e[0][c4]; E01 = es.x; E23 = es.y; }
#pragma unroll
        for (int s = 1; s < SUBS; s++) {
            ulonglong2 es = s_e[s][c4];
            E01 = f2fma(A8_01, E01, es.x);
            E23 = f2fma(A8_23, E23, es.y);
        }
        u64 A32_01, A32_23;  // a^32 = block decay
        t = f2mul(A8_01, A8_01); A32_01 = f2mul(t, t);
        t = f2mul(A8_23, A8_23); A32_23 = f2mul(t, t);

        u64* cp = g_carry + ((size_t)(b * NCH + k)) * CC + ch0;
        // publish aggregate (flag=1); 8B words carry flag+value together (atomic, no fence)
        asm volatile("st.global.v2.u64 [%0], {%1, %2};" ::
            "l"(cp), "l"((1ULL << 32) | (u64)(unsigned)E01), "l"((1ULL << 32) | (E01 >> 32)) : "memory");
        asm volatile("st.global.v2.u64 [%0], {%1, %2};" ::
            "l"(cp + 2), "l"((1ULL << 32) | (u64)(unsigned)E23), "l"((1ULL << 32) | (E23 >> 32)) : "memory");

        float y0s[4];
        { ulonglong2 yv = *((const ulonglong2*)(y0 + b * CC + ch0));
          y0s[0] = lo32(yv.x); y0s[1] = hi32(yv.x); y0s[2] = lo32(yv.y); y0s[3] = hi32(yv.y); }

        u64 bs01, bs23;
        if (k == 0) {
            bs01 = pk(y0s[0], y0s[1]); bs23 = pk(y0s[2], y0s[3]);
        } else {
            // ---- lookback: batched 4-pred rounds, per-lane prefix short-circuit ----
            const float A32s[4] = { lo32(A32_01), hi32(A32_01), lo32(A32_23), hi32(A32_23) };
            float acc[4] = {0.f, 0.f, 0.f, 0.f};
            float mm[4]  = {1.f, 1.f, 1.f, 1.f};
            unsigned dn = 0;
            const u64* cb = g_carry + (size_t)b * NCH * CC + ch0;
            int j = k - 1;
            for (;;) {
                const int g = (j + 1 < 4) ? (j + 1) : 4;
                u64 pv[4][4];
                bool rdy;
                do {
                    rdy = true;
                    for (int p = 0; p < g; p++) {
                        const u64* pp = cb + (size_t)(j - p) * CC;
                        u64 r0, r1, r2, r3;
                        asm volatile("ld.volatile.global.v2.u64 {%0,%1}, [%2];"
                                     : "=l"(r0), "=l"(r1) : "l"(pp) : "memory");
                        asm volatile("ld.volatile.global.v2.u64 {%0,%1}, [%2];"
                                     : "=l"(r2), "=l"(r3) : "l"(pp + 2) : "memory");
                        pv[p][0] = r0; pv[p][1] = r1; pv[p][2] = r2; pv[p][3] = r3;
                        if (!((r0 >> 32) && (r1 >> 32) && (r2 >> 32) && (r3 >> 32))) rdy = false;
                    }
                } while (!rdy);
                for (int p = 0; p < g; p++) {
#pragma unroll
                    for (int l = 0; l < 4; l++) {
                        if (!((dn >> l) & 1)) {
                            const u64 v = pv[p][l];
                            acc[l] = fmaf(mm[l], __uint_as_float((unsigned)v), acc[l]);
                            if ((unsigned)(v >> 32) == 2u) dn |= 1u << l;  // inclusive prefix
                            else mm[l] *= A32s[l];                         // aggregate
                        }
                    }
                }
                j -= g;
                if (dn == 0xF) break;
                if (j < 0) {  // folded all aggregates; fold in the initial state
#pragma unroll
                    for (int l = 0; l < 4; l++)
                        if (!((dn >> l) & 1)) acc[l] = fmaf(mm[l], y0s[l], acc[l]);
                    break;
                }
            }
            bs01 = pk(acc[0], acc[1]); bs23 = pk(acc[2], acc[3]);
        }

        // publish inclusive prefix (flag=2) for downstream short-circuit
        const u64 P01 = f2fma(A32_01, bs01, E01);
        const u64 P23 = f2fma(A32_23, bs23, E23);
        asm volatile("st.global.v2.u64 [%0], {%1, %2};" ::
            "l"(cp), "l"((2ULL << 32) | (u64)(unsigned)P01), "l"((2ULL << 32) | (P01 >> 32)) : "memory");
        asm volatile("st.global.v2.u64 [%0], {%1, %2};" ::
            "l"(cp + 2), "l"((2ULL << 32) | (u64)(unsigned)P23), "l"((2ULL << 32) | (P23 >> 32)) : "memory");

        s_bs[c4] = make_ulonglong2(bs01, bs23);
    }
    __syncthreads();

    // ---- Phase C: entering value for this sub-chunk, then replay from smem stash ----
    u64 y01, y23;
    { ulonglong2 bsv = s_bs[c4]; y01 = bsv.x; y23 = bsv.y; }
#pragma unroll
    for (int s = 0; s < SUBS - 1; s++) {   // s < sub (sub is warp-uniform)
        if (s < sub) {
            ulonglong2 es = s_e[s][c4];
            y01 = f2fma(A8_01, y01, es.x);
            y23 = f2fma(A8_23, y23, es.y);
        }
    }
    ulonglong2* op = (ulonglong2*)out + (base >> 2);
#pragma unroll
    for (int i = 0; i < LT; i++) {
        ulonglong2 xv = s_x[i][tid];
        y01 = f2fma(a01, y01, f2mul(w01, xv.x));
        y23 = f2fma(a23, y23, f2mul(w23, xv.y));
        ulonglong2 yv; yv.x = y01; yv.y = y23;
        __stcs(op + i * (CC / 4), yv);
    }
}

extern "C" void kernel_launch(void* const* d_in, const int* in_sizes, int n_in,
                              void* d_out, int out_size) {
    const float* x      = (const float*)d_in[0];  // [B, T, C]
    const float* y0     = (const float*)d_in[1];  // [B, C]
    const float* smooth = (const float*)d_in[2];  // [C]
    float* out          = (float*)d_out;

    const int B = in_sizes[0] / (TT * CC);

    ema_clear_kernel<<<(MAXB * NCH * CC / 2) / 256, 256>>>();
    ema_scan_kernel<<<B * NCH, 256>>>(x, y0, smooth, out);
}

// round 4
// speedup vs baseline: 3.0557x; 3.0557x over previous
#include <cuda_runtime.h>

// EMA y_t = (1-w)*y_{t-1} + w*x_t — decoupled-lookback scan, v3.
// v1 structure (thread = channel, 32-timestep register stash) with one key
// change: grid is ordered batch-fast / chunk-slow, so each scheduling wave
// holds only ~37 chunk-levels per chain instead of full 256-chunk chains.
// Lookback then folds <=~37 aggregates (5 rounds) instead of up to 255
// (32 rounds) per wave. Stash holds w*x (saves the Phase C FMULs).

#define TT   8192
#define CC   256
#define LL   32
#define NCH  (TT / LL)   // 256 chunks per batch row
#define MAXB 16

// packed carry: high 32 = flag (0 empty / 1 aggregate / 2 inclusive prefix),
// low 32 = float payload. Zeroed each launch.
__device__ unsigned long long g_carry[MAXB * NCH * CC];

__global__ void ema_clear_kernel() {
    int i = blockIdx.x * blockDim.x + threadIdx.x;
    ((ulonglong2*)g_carry)[i] = make_ulonglong2(0ULL, 0ULL);
}

__global__ __launch_bounds__(CC, 4) void ema_scan_kernel(
    const float* __restrict__ x,
    const float* __restrict__ y0,
    const float* __restrict__ smooth,
    float* __restrict__ out,
    int B)
{
    // batch-fast decomposition: predecessors (k-1, b) are exactly B bids lower,
    // so concurrent waves span many batches but few chunk-levels per chain.
    const int b = blockIdx.x % B;
    const int k = blockIdx.x / B;
    const int c = threadIdx.x;

    const float w = fminf(fmaxf(smooth[c], 0.0f), 1.0f);
    const float a = 1.0f - w;

    // ---- Phase A: load chunk, stash w*x, compute zero-start aggregate ----
    const float* xp = x + ((size_t)(b * TT + k * LL) * CC + c);
    float wx[LL];
#pragma unroll
    for (int i = 0; i < LL; i++) wx[i] = w * __ldcs(xp + i * CC);

    float e = 0.0f;
#pragma unroll
    for (int i = 0; i < LL; i++) e = fmaf(a, e, wx[i]);

    // A_L = a^32 via 5 squarings
    float A2 = a * a;
    float A4 = A2 * A2;
    float A8 = A4 * A4;
    float A16 = A8 * A8;
    const float AL = A16 * A16;

    volatile unsigned long long* cb = g_carry + (size_t)(b * NCH) * CC;

    // publish aggregate (flag=1): single aligned 8B store = atomic, no fence
    cb[(size_t)k * CC + c] =
        (1ULL << 32) | (unsigned long long)__float_as_uint(e);

    // ---- Lookback: fold predecessor aggregates, short-circuit on prefixes ----
    float acc;
    if (k == 0) {
        acc = y0[b * CC + c];
    } else {
        acc = 0.0f;
        float m = 1.0f;
        int j = k - 1;
        bool done = false;
        while (!done) {
            const int g = (j + 1 < 8) ? (j + 1) : 8;
            unsigned long long v[8];
            bool allset;
            do {  // batched spin: 8 independent volatile 8B reads per round
                allset = true;
#pragma unroll
                for (int u = 0; u < 8; u++) {
                    if (u < g) {
                        v[u] = cb[(size_t)(j - u) * CC + c];
                        if ((unsigned)(v[u] >> 32) == 0u) allset = false;
                    }
                }
            } while (!allset);
#pragma unroll
            for (int u = 0; u < 8; u++) {
                if (u < g) {
                    const unsigned f = (unsigned)(v[u] >> 32);
                    const float val = __uint_as_float((unsigned)(v[u] & 0xFFFFFFFFu));
                    acc = fmaf(m, val, acc);
                    if (f == 2u) { done = true; break; }  // inclusive prefix
                    m *= AL;                              // zero-start aggregate
                }
            }
            if (!done) {
                j -= g;
                if (j < 0) {  // all aggregates folded; add initial-state term
                    acc = fmaf(m, y0[b * CC + c], acc);
                    done = true;
                }
            }
        }
    }

    // publish inclusive prefix (flag=2) so downstream chunks short-circuit
    const float P = fmaf(AL, acc, e);
    cb[(size_t)k * CC + c] =
        (2ULL << 32) | (unsigned long long)__float_as_uint(P);

    // ---- Phase C: replay recurrence from the w*x stash, stream outputs ----
    float y = acc;
    float* op = out + ((size_t)(b * TT + k * LL) * CC + c);
#pragma unroll
    for (int i = 0; i < LL; i++) {
        y = fmaf(a, y, wx[i]);
        __stcs(op + i * CC, y);
    }
}

extern "C" void kernel_launch(void* const* d_in, const int* in_sizes, int n_in,
                              void* d_out, int out_size) {
    const float* x      = (const float*)d_in[0];  // [B, T, C]
    const float* y0     = (const float*)d_in[1];  // [B, C]
    const float* smooth = (const float*)d_in[2];  // [C]
    float* out          = (float*)d_out;

    const int B = in_sizes[0] / (TT * CC);

    ema_clear_kernel<<<(MAXB * NCH * CC / 2) / 256, 256>>>();
    ema_scan_kernel<<<B * NCH, CC>>>(x, y0, smooth, out, B);
}